// round 16
// baseline (speedup 1.0000x reference)
#include <cuda_runtime.h>
#include <cuda_fp16.h>
#include <math.h>

#define BB 4
#define NN 1024
#define CC 768
#define HH 12
#define HD 64
#define QKV3 (3*CC)          // 2304
#define MROWS (2*BB*NN)      // 8192
#define PERSB (HH*NN*HD)     // 786432 elems per (stream,b)

// -------- scratch (device globals; no allocation) --------
__device__ __half g_q  [2*BB*HH*NN*HD];   // [s][b][h][n][d]
__device__ __half g_k  [2*BB*HH*NN*HD];   // [s][b][h][n][d]
__device__ __half g_v  [2*BB*HH*NN*HD];   // [s][b][h][n][d]
__device__ __half g_ctx[2*BB*HH*NN*HD];   // [p][b][h][n][d]
__device__ __half g_x  [MROWS*CC];        // fp16 [before;after]
__device__ __half g_wq [QKV3*CC];         // fp16 W_qkv
__device__ __half g_wp [CC*CC];           // fp16 W_proj

// -------- helpers --------
__device__ __forceinline__ float ex2f(float x) {
    float y; asm("ex2.approx.ftz.f32 %0, %1;" : "=f"(y) : "f"(x)); return y;
}
__device__ __forceinline__ unsigned pack2(float lo, float hi) {
    unsigned r; asm("cvt.rn.f16x2.f32 %0, %1, %2;" : "=r"(r) : "f"(hi), "f"(lo));
    return r;
}
__device__ __forceinline__ void mma16(float* c, const unsigned* a, const unsigned* b) {
    asm volatile("mma.sync.aligned.m16n8k16.row.col.f32.f16.f16.f32 "
        "{%0,%1,%2,%3}, {%4,%5,%6,%7}, {%8,%9}, {%0,%1,%2,%3};"
        : "+f"(c[0]), "+f"(c[1]), "+f"(c[2]), "+f"(c[3])
        : "r"(a[0]), "r"(a[1]), "r"(a[2]), "r"(a[3]), "r"(b[0]), "r"(b[1]));
}
__device__ __forceinline__ void ldsm4(unsigned& r0, unsigned& r1, unsigned& r2,
                                      unsigned& r3, unsigned addr) {
    asm volatile("ldmatrix.sync.aligned.m8n8.x4.shared.b16 {%0,%1,%2,%3}, [%4];"
        : "=r"(r0), "=r"(r1), "=r"(r2), "=r"(r3) : "r"(addr));
}
__device__ __forceinline__ void ldsm4t(unsigned& r0, unsigned& r1, unsigned& r2,
                                       unsigned& r3, unsigned addr) {
    asm volatile("ldmatrix.sync.aligned.m8n8.x4.trans.shared.b16 {%0,%1,%2,%3}, [%4];"
        : "=r"(r0), "=r"(r1), "=r"(r2), "=r"(r3) : "r"(addr));
}
__device__ __forceinline__ unsigned s2u(const void* p) {
    return (unsigned)__cvta_generic_to_shared(p);
}
__device__ __forceinline__ void cp16(unsigned dst, const void* src) {
    asm volatile("cp.async.cg.shared.global [%0], [%1], 16;" :: "r"(dst), "l"(src));
}
#define CPCOMMIT() asm volatile("cp.async.commit_group;")

// -------- bulk-DMA + mbarrier helpers (GEMM staging) --------
__device__ __forceinline__ void mbar_init(unsigned a, unsigned cnt) {
    asm volatile("mbarrier.init.shared.b64 [%0], %1;" :: "r"(a), "r"(cnt) : "memory");
}
__device__ __forceinline__ void mbar_expect(unsigned a, unsigned bytes) {
    asm volatile("mbarrier.arrive.expect_tx.shared.b64 _, [%0], %1;"
        :: "r"(a), "r"(bytes) : "memory");
}
__device__ __forceinline__ void bulk128(unsigned dst, const void* src, unsigned mbar) {
    asm volatile("cp.async.bulk.shared::cta.global.mbarrier::complete_tx::bytes "
        "[%0], [%1], 128, [%2];" :: "r"(dst), "l"(src), "r"(mbar) : "memory");
}
__device__ __forceinline__ void mbar_wait(unsigned a, unsigned ph) {
    asm volatile("{\n\t.reg .pred P;\n\tWL_%=:\n\t"
        "mbarrier.try_wait.parity.acquire.cta.shared::cta.b64 P, [%0], %1, 0x989680;\n\t"
        "@P bra.uni WD_%=;\n\tbra.uni WL_%=;\n\tWD_%=:\n\t}"
        :: "r"(a), "r"(ph) : "memory");
}

// GEMM staging (bulk): padded 144B rows, 128B payload per row.
#define PRS   144             // padded row stride (9 x 16B, LDSM conflict-free)
#define ATILE (128*PRS)       // 18432 B per operand tile
#define STGB  (2*ATILE)       // 36864 B per stage (A + B)
#define GHDR  64              // mbarriers at smem[0,8,16]
#define GSMEMB (GHDR + 3*STGB)   // 110656 B
#define STG_TX 32768          // actual bytes per stage (256 rows x 128B)

// =====================================================================
// Kernel 0: convert inputs to fp16 (once). 8 floats per thread.
// =====================================================================
#define XQ8 (MROWS*CC/8)     // 786432
#define WQ8 (QKV3*CC/8)      // 221184
#define PQ8 (CC*CC/8)        // 73728
#define PR8 (XQ8+WQ8+PQ8)    // 1081344 = 4224*256

__global__ __launch_bounds__(256) void preround_kernel(
    const float* __restrict__ before, const float* __restrict__ after,
    const float* __restrict__ Wqkv, const float* __restrict__ Wp)
{
    int i = blockIdx.x*256 + threadIdx.x;
    const float* src; __half* dst;
    if (i < XQ8) {
        src = (i < XQ8/2) ? before + (size_t)i*8 : after + (size_t)(i - XQ8/2)*8;
        dst = g_x + (size_t)i*8;
    } else if (i < XQ8 + WQ8) {
        src = Wqkv + (size_t)(i - XQ8)*8;
        dst = g_wq + (size_t)(i - XQ8)*8;
    } else {
        src = Wp + (size_t)(i - XQ8 - WQ8)*8;
        dst = g_wp + (size_t)(i - XQ8 - WQ8)*8;
    }
    float4 v0 = ((const float4*)src)[0];
    float4 v1 = ((const float4*)src)[1];
    uint4 o;
    o.x = pack2(v0.x, v0.y); o.y = pack2(v0.z, v0.w);
    o.z = pack2(v1.x, v1.y); o.w = pack2(v1.z, v1.w);
    *(uint4*)dst = o;
}

// =====================================================================
// Kernel 1: QKV GEMM, 128 thr = 4 warps (2m x 2n), warp tile 64x64,
// K-step 64, 3-stage BULK-DMA staging + REGISTER LayerNorm epilogue.
// =====================================================================
__global__ __launch_bounds__(128, 2) void qkv_gemm_mma(
    const float* __restrict__ ln_g, const float* __restrict__ ln_b)
{
    extern __shared__ __align__(128) unsigned char sq[];
    __shared__ float s_lng[64], s_lnb[64];
    const int tid = threadIdx.x;
    if (tid < 64) { s_lng[tid] = ln_g[tid]; s_lnb[tid] = ln_b[tid]; }

    const int warp = tid >> 5, lane = tid & 31;
    const int wm = warp >> 1, wn = warp & 1;
    const int g = lane >> 2, t = lane & 3;
    const int mt = blockIdx.y;
    const int bn = blockIdx.x * 128;
    const unsigned smb = s2u(sq);

    const __half* abase = g_x + (size_t)(mt*128)*CC;      // row r: +r*CC, chunk c: +c*64
    const __half* bbase = g_wq + (size_t)bn*CC;

    const unsigned aoffl = (lane & 15)*PRS + (lane >> 4)*16;
    const unsigned blinl = ((lane & 7) + ((lane >> 4) & 1)*8)*PRS + ((lane >> 3) & 1)*16;

    if (tid == 0) { mbar_init(smb+0,1); mbar_init(smb+8,1); mbar_init(smb+16,1); }
    __syncthreads();

    // stage chunks 0,1 (warp 0)
    if (warp == 0) {
        #pragma unroll
        for (int c = 0; c < 2; c++) {
            unsigned mb = smb + c*8;
            if (lane == 0) mbar_expect(mb, STG_TX);
            __syncwarp();
            unsigned dA = smb + GHDR + c*STGB;
            unsigned dB = dA + ATILE;
            #pragma unroll
            for (int i = 0; i < 4; i++) {
                int r = lane + i*32;
                bulk128(dA + r*PRS, abase + (size_t)r*CC + c*64, mb);
                bulk128(dB + r*PRS, bbase + (size_t)r*CC + c*64, mb);
            }
        }
    }

    float acc[4][8][4] = {};

    for (int c = 0; c < 12; c++) {
        __syncthreads();          // all warps done reading buf[(c+2)%3] (chunk c-1)
        if (c + 2 < 12 && warp == 0) {
            int cn = c + 2;
            unsigned mb = smb + (cn % 3)*8;
            if (lane == 0) mbar_expect(mb, STG_TX);
            __syncwarp();
            unsigned dA = smb + GHDR + (cn % 3)*STGB;
            unsigned dB = dA + ATILE;
            #pragma unroll
            for (int i = 0; i < 4; i++) {
                int r = lane + i*32;
                bulk128(dA + r*PRS, abase + (size_t)r*CC + cn*64, mb);
                bulk128(dB + r*PRS, bbase + (size_t)r*CC + cn*64, mb);
            }
        }
        mbar_wait(smb + (c % 3)*8, (unsigned)((c/3) & 1));

        const unsigned Ab = smb + GHDR + (c % 3)*STGB;
        const unsigned Bb = Ab + ATILE;
        #pragma unroll
        for (int kk = 0; kk < 4; kk++) {
            unsigned a[4][4], bq[8][2];
            #pragma unroll
            for (int mf = 0; mf < 4; mf++)
                ldsm4(a[mf][0], a[mf][1], a[mf][2], a[mf][3],
                      Ab + (wm*64 + mf*16)*PRS + kk*32 + aoffl);
            #pragma unroll
            for (int g2 = 0; g2 < 4; g2++) {
                unsigned r0, r1, r2, r3;
                ldsm4(r0, r1, r2, r3, Bb + (wn*64 + g2*16)*PRS + kk*32 + blinl);
                bq[2*g2][0] = r0; bq[2*g2][1] = r1;
                bq[2*g2+1][0] = r2; bq[2*g2+1][1] = r3;
            }
            #pragma unroll
            for (int mf = 0; mf < 4; mf++)
                #pragma unroll
                for (int nf = 0; nf < 8; nf++)
                    mma16(acc[mf][nf], a[mf], bq[nf]);
        }
    }

    // register-resident LayerNorm epilogue (wn column == one 64-wide head)
    const int cb = bn + wn*64;
    const int tq = cb / CC;                 // 0=q,1=k,2=v
    const int h  = (cb % CC) >> 6;
    const int gm0 = mt*128;
    const int s = gm0 >> 12, b = (gm0 >> 10) & 3;
    __half* dbase = (tq == 0 ? g_q : tq == 1 ? g_k : g_v)
                  + ((((size_t)(s*BB+b)*HH + h)*NN) + (gm0 & 1023))*HD;

    #pragma unroll
    for (int mf = 0; mf < 4; mf++) {
        float sum0 = 0.f, sq0 = 0.f, sum1 = 0.f, sq1 = 0.f;
        #pragma unroll
        for (int nf = 0; nf < 8; nf++) {
            float a0 = acc[mf][nf][0], a1 = acc[mf][nf][1];
            float a2 = acc[mf][nf][2], a3 = acc[mf][nf][3];
            sum0 += a0 + a1; sq0 += a0*a0 + a1*a1;
            sum1 += a2 + a3; sq1 += a2*a2 + a3*a3;
        }
        sum0 += __shfl_xor_sync(0xffffffffu, sum0, 1);
        sum0 += __shfl_xor_sync(0xffffffffu, sum0, 2);
        sq0  += __shfl_xor_sync(0xffffffffu, sq0, 1);
        sq0  += __shfl_xor_sync(0xffffffffu, sq0, 2);
        sum1 += __shfl_xor_sync(0xffffffffu, sum1, 1);
        sum1 += __shfl_xor_sync(0xffffffffu, sum1, 2);
        sq1  += __shfl_xor_sync(0xffffffffu, sq1, 1);
        sq1  += __shfl_xor_sync(0xffffffffu, sq1, 2);
        float mu0 = sum0 * (1.f/64.f);
        float rs0 = rsqrtf(sq0 * (1.f/64.f) - mu0*mu0 + 1e-5f);
        float mu1 = sum1 * (1.f/64.f);
        float rs1 = rsqrtf(sq1 * (1.f/64.f) - mu1*mu1 + 1e-5f);

        int r0 = wm*64 + mf*16 + g;
        __half* d0 = dbase + (size_t)r0*HD;
        __half* d1 = dbase + (size_t)(r0+8)*HD;
        #pragma unroll
        for (int nf = 0; nf < 8; nf++) {
            int col = nf*8 + 2*t;
            float g0 = s_lng[col], g1 = s_lng[col+1];
            float b0 = s_lnb[col], b1 = s_lnb[col+1];
            *(__half2*)(d0 + col) = __floats2half2_rn(
                (acc[mf][nf][0]-mu0)*rs0*g0 + b0,
                (acc[mf][nf][1]-mu0)*rs0*g1 + b1);
            *(__half2*)(d1 + col) = __floats2half2_rn(
                (acc[mf][nf][2]-mu1)*rs1*g0 + b0,
                (acc[mf][nf][3]-mu1)*rs1*g1 + b1);
        }
    }
}

// =====================================================================
// Kernel 2 (r14 winner, unchanged): attention, 128 thr = 4 warps, warp
// owns 32 q-rows (2 m-frags), kv-tile 128, 2 CTAs/SM, cp.async staging.
// =====================================================================
#define ARS 144
#define QB  0
#define KB0 (128*ARS)         // 18432
#define VB0 (KB0 + 2*128*ARS) // 55296
#define ATTN_SMEM (VB0 + 2*128*ARS)   // 92160

__global__ __launch_bounds__(128, 2) void attn_mma() {
    extern __shared__ __align__(16) unsigned char sa[];
    const unsigned smb = s2u(sa);

    const int bx = blockIdx.x;
    const int qt = bx & 7;
    const int h  = (bx >> 3) % 12;
    const int b  = (bx / 96) & 3;
    const int p  = bx / 384;
    const int qs = 1 - p, kvs = p;

    const __half* qptr = g_q + (((size_t)(qs*BB+b)*HH + h)*NN + qt*128)*HD;
    const __half* kptr = g_k + (((size_t)(kvs*BB+b)*HH + h)*NN)*HD;
    const __half* vptr = g_v + (((size_t)(kvs*BB+b)*HH + h)*NN)*HD;

    const int tid = threadIdx.x, w = tid >> 5, lane = tid & 31;
    const int g = lane >> 2, t = lane & 3;

    const unsigned aoffA = ((lane & 15)*ARS + (lane >> 4)*16);
    const unsigned boffK = (((lane & 7) + ((lane >> 4) & 1)*8)*ARS + ((lane >> 3) & 1)*16);
    const unsigned boffV = (((lane & 7) + ((lane >> 3) & 1)*8)*ARS + (lane >> 4)*16);

    int srow[8], sch[8];
    #pragma unroll
    for (int i = 0; i < 8; i++) {
        int id = tid + i*128; srow[i] = id >> 3; sch[i] = id & 7;
    }

    #pragma unroll
    for (int i = 0; i < 8; i++) {
        cp16(smb + KB0 + srow[i]*ARS + sch[i]*16, kptr + srow[i]*64 + sch[i]*8);
        cp16(smb + VB0 + srow[i]*ARS + sch[i]*16, vptr + srow[i]*64 + sch[i]*8);
    }
    CPCOMMIT();

    #pragma unroll
    for (int i = 0; i < 8; i++) {
        int id = tid + i*128, row = id >> 3, ch = id & 7;
        *(uint4*)(sa + QB + row*ARS + ch*16) = *(const uint4*)(qptr + row*64 + ch*8);
    }
    __syncthreads();
    unsigned q[2][4][4];
    #pragma unroll
    for (int mf = 0; mf < 2; mf++)
        #pragma unroll
        for (int kk = 0; kk < 4; kk++)
            ldsm4(q[mf][kk][0], q[mf][kk][1], q[mf][kk][2], q[mf][kk][3],
                  smb + QB + (w*32 + mf*16)*ARS + kk*32 + aoffA);

    const float SC = 0.125f * 1.44269504088896f;
    float o[2][8][4] = {};
    float mm[2][2] = {{-1e30f,-1e30f},{-1e30f,-1e30f}};
    float ll[2][2] = {{0.f,0.f},{0.f,0.f}};

    for (int kc = 0; kc < 8; kc++) {
        __syncthreads();
        if (kc < 7) {
            const __half* kp = kptr + (kc+1)*128*64;
            const __half* vp = vptr + (kc+1)*128*64;
            const unsigned kb = smb + KB0 + ((kc+1)&1)*(128*ARS);
            const unsigned vb = smb + VB0 + ((kc+1)&1)*(128*ARS);
            #pragma unroll
            for (int i = 0; i < 8; i++) {
                cp16(kb + srow[i]*ARS + sch[i]*16, kp + srow[i]*64 + sch[i]*8);
                cp16(vb + srow[i]*ARS + sch[i]*16, vp + srow[i]*64 + sch[i]*8);
            }
            CPCOMMIT();
            asm volatile("cp.async.wait_group 1;");
        } else {
            asm volatile("cp.async.wait_group 0;");
        }
        __syncthreads();

        const unsigned Kb = smb + KB0 + (kc&1)*(128*ARS);
        const unsigned Vb = smb + VB0 + (kc&1)*(128*ARS);

        #pragma unroll
        for (int half = 0; half < 2; half++) {
            const unsigned Kh = Kb + half*64*ARS;
            const unsigned Vh = Vb + half*64*ARS;

            float s[2][8][4] = {};
            #pragma unroll
            for (int kk = 0; kk < 4; kk++) {
                #pragma unroll
                for (int j2 = 0; j2 < 4; j2++) {
                    unsigned r0, r1, r2, r3;
                    ldsm4(r0, r1, r2, r3, Kh + (j2*16)*ARS + kk*32 + boffK);
                    unsigned bf0[2] = {r0, r1}, bf1[2] = {r2, r3};
                    #pragma unroll
                    for (int mf = 0; mf < 2; mf++) {
                        mma16(s[mf][2*j2], q[mf][kk], bf0);
                        mma16(s[mf][2*j2+1], q[mf][kk], bf1);
                    }
                }
            }

            #pragma unroll
            for (int mf = 0; mf < 2; mf++) {
                float mx0 = -1e30f, mx1 = -1e30f;
                #pragma unroll
                for (int nf = 0; nf < 8; nf++) {
                    #pragma unroll
                    for (int j = 0; j < 4; j++) s[mf][nf][j] *= SC;
                    mx0 = fmaxf(mx0, fmaxf(s[mf][nf][0], s[mf][nf][1]));
                    mx1 = fmaxf(mx1, fmaxf(s[mf][nf][2], s[mf][nf][3]));
                }
                mx0 = fmaxf(mx0, __shfl_xor_sync(0xffffffffu, mx0, 1));
                mx0 = fmaxf(mx0, __shfl_xor_sync(0xffffffffu, mx0, 2));
                mx1 = fmaxf(mx1, __shfl_xor_sync(0xffffffffu, mx1, 1));
                mx1 = fmaxf(mx1, __shfl_xor_sync(0xffffffffu, mx1, 2));
                float M0 = fmaxf(mm[mf][0], mx0), M1 = fmaxf(mm[mf][1], mx1);
                float c0 = ex2f(mm[mf][0] - M0), c1 = ex2f(mm[mf][1] - M1);
                float ls0 = 0.f, ls1 = 0.f;
                #pragma unroll
                for (int nf = 0; nf < 8; nf++) {
                    s[mf][nf][0] = ex2f(s[mf][nf][0] - M0);
                    s[mf][nf][1] = ex2f(s[mf][nf][1] - M0);
                    s[mf][nf][2] = ex2f(s[mf][nf][2] - M1);
                    s[mf][nf][3] = ex2f(s[mf][nf][3] - M1);
                    ls0 += s[mf][nf][0] + s[mf][nf][1];
                    ls1 += s[mf][nf][2] + s[mf][nf][3];
                }
                ls0 += __shfl_xor_sync(0xffffffffu, ls0, 1);
                ls0 += __shfl_xor_sync(0xffffffffu, ls0, 2);
                ls1 += __shfl_xor_sync(0xffffffffu, ls1, 1);
                ls1 += __shfl_xor_sync(0xffffffffu, ls1, 2);
                ll[mf][0] = ll[mf][0]*c0 + ls0;
                ll[mf][1] = ll[mf][1]*c1 + ls1;
                mm[mf][0] = M0; mm[mf][1] = M1;
                #pragma unroll
                for (int nf = 0; nf < 8; nf++) {
                    o[mf][nf][0] *= c0; o[mf][nf][1] *= c0;
                    o[mf][nf][2] *= c1; o[mf][nf][3] *= c1;
                }
            }

            #pragma unroll
            for (int kc2 = 0; kc2 < 4; kc2++) {
                unsigned a2[2][4];
                #pragma unroll
                for (int mf = 0; mf < 2; mf++) {
                    a2[mf][0] = pack2(s[mf][2*kc2][0],   s[mf][2*kc2][1]);
                    a2[mf][1] = pack2(s[mf][2*kc2][2],   s[mf][2*kc2][3]);
                    a2[mf][2] = pack2(s[mf][2*kc2+1][0], s[mf][2*kc2+1][1]);
                    a2[mf][3] = pack2(s[mf][2*kc2+1][2], s[mf][2*kc2+1][3]);
                }
                #pragma unroll
                for (int j = 0; j < 4; j++) {
                    unsigned r0, r1, r2, r3;
                    ldsm4t(r0, r1, r2, r3, Vh + (kc2*16)*ARS + j*32 + boffV);
                    unsigned bf0[2] = {r0, r1}, bf1[2] = {r2, r3};
                    #pragma unroll
                    for (int mf = 0; mf < 2; mf++) {
                        mma16(o[mf][2*j], a2[mf], bf0);
                        mma16(o[mf][2*j+1], a2[mf], bf1);
                    }
                }
            }
        }
    }

    const int qrow = qt*128 + w*32;
    #pragma unroll
    for (int mf = 0; mf < 2; mf++) {
        float inv0 = 1.f / ll[mf][0], inv1 = 1.f / ll[mf][1];
        __half* op = g_ctx + (((size_t)(p*BB+b)*HH + h)*NN + qrow + mf*16)*HD;
        #pragma unroll
        for (int nf = 0; nf < 8; nf++) {
            *(__half2*)(op + g*64 + nf*8 + 2*t) =
                __floats2half2_rn(o[mf][nf][0]*inv0, o[mf][nf][1]*inv0);
            *(__half2*)(op + (g+8)*64 + nf*8 + 2*t) =
                __floats2half2_rn(o[mf][nf][2]*inv1, o[mf][nf][3]*inv1);
        }
    }
}

// =====================================================================
// Kernel 3: projection GEMM, 256 thr = 8 warps (2m x 4n), warp tile
// 64x32, K-step 64 = one head, 3-stage BULK-DMA staging.
// + bias + q-residual -> f32 out.
// =====================================================================
__global__ __launch_bounds__(256, 2) void proj_gemm_mma(
    const float* __restrict__ bias, float* __restrict__ out)
{
    extern __shared__ __align__(128) unsigned char sp[];
    const int tid = threadIdx.x;
    const int warp = tid >> 5, lane = tid & 31;
    const int wm = warp >> 2, wn = warp & 3;
    const int g = lane >> 2, t = lane & 3;
    const int mt = blockIdx.y;
    const int bn = blockIdx.x * 128;
    const unsigned smb = s2u(sp);

    // per-lane A row bases (rows lane, lane+32, lane+64, lane+96)
    const __half* arow[4];
    #pragma unroll
    for (int i = 0; i < 4; i++) {
        int r = lane + i*32;
        int gm = mt*128 + r;
        int pp = gm >> 12, b2 = (gm >> 10) & 3, n = gm & 1023;
        arow[i] = g_ctx + (size_t)(pp*BB + b2)*PERSB + (size_t)n*HD;
    }
    const __half* bbase = g_wp + (size_t)bn*CC;

    const unsigned aoffl = (lane & 15)*PRS + (lane >> 4)*16;
    const unsigned blinl = ((lane & 7) + ((lane >> 4) & 1)*8)*PRS + ((lane >> 3) & 1)*16;

    if (tid == 0) { mbar_init(smb+0,1); mbar_init(smb+8,1); mbar_init(smb+16,1); }
    __syncthreads();

    // stage chunks 0,1 (warp 0): A chunk c = head c -> +c*NN*HD; B -> +c*64
    if (warp == 0) {
        #pragma unroll
        for (int c = 0; c < 2; c++) {
            unsigned mb = smb + c*8;
            if (lane == 0) mbar_expect(mb, STG_TX);
            __syncwarp();
            unsigned dA = smb + GHDR + c*STGB;
            unsigned dB = dA + ATILE;
            #pragma unroll
            for (int i = 0; i < 4; i++) {
                int r = lane + i*32;
                bulk128(dA + r*PRS, arow[i] + (size_t)c*(NN*HD), mb);
                bulk128(dB + r*PRS, bbase + (size_t)r*CC + c*64, mb);
            }
        }
    }

    float acc[4][4][4] = {};

    for (int c = 0; c < 12; c++) {
        __syncthreads();
        if (c + 2 < 12 && warp == 0) {
            int cn = c + 2;
            unsigned mb = smb + (cn % 3)*8;
            if (lane == 0) mbar_expect(mb, STG_TX);
            __syncwarp();
            unsigned dA = smb + GHDR + (cn % 3)*STGB;
            unsigned dB = dA + ATILE;
            #pragma unroll
            for (int i = 0; i < 4; i++) {
                int r = lane + i*32;
                bulk128(dA + r*PRS, arow[i] + (size_t)cn*(NN*HD), mb);
                bulk128(dB + r*PRS, bbase + (size_t)r*CC + cn*64, mb);
            }
        }
        mbar_wait(smb + (c % 3)*8, (unsigned)((c/3) & 1));

        const unsigned Ab = smb + GHDR + (c % 3)*STGB;
        const unsigned Bb = Ab + ATILE;
        #pragma unroll
        for (int kk = 0; kk < 4; kk++) {
            unsigned a[4][4], bq[4][2];
            #pragma unroll
            for (int mf = 0; mf < 4; mf++)
                ldsm4(a[mf][0], a[mf][1], a[mf][2], a[mf][3],
                      Ab + (wm*64 + mf*16)*PRS + kk*32 + aoffl);
            #pragma unroll
            for (int g2 = 0; g2 < 2; g2++) {
                unsigned r0, r1, r2, r3;
                ldsm4(r0, r1, r2, r3, Bb + (wn*32 + g2*16)*PRS + kk*32 + blinl);
                bq[2*g2][0] = r0; bq[2*g2][1] = r1;
                bq[2*g2+1][0] = r2; bq[2*g2+1][1] = r3;
            }
            #pragma unroll
            for (int mf = 0; mf < 4; mf++)
                #pragma unroll
                for (int nf = 0; nf < 4; nf++)
                    mma16(acc[mf][nf], a[mf], bq[nf]);
        }
    }

    // epilogue: bias + fp16 flat-q residual -> f32 d_out
    #pragma unroll
    for (int mf = 0; mf < 4; mf++) {
        #pragma unroll
        for (int rr = 0; rr < 2; rr++) {
            int gm = mt*128 + wm*64 + mf*16 + g + rr*8;
            int pp = gm >> 12, b2 = (gm >> 10) & 3, n = gm & 1023;
            const __half* qres = g_q + (size_t)((1-pp)*BB + b2)*PERSB + (size_t)n*CC;
            #pragma unroll
            for (int nf = 0; nf < 4; nf++) {
                int col = bn + wn*32 + nf*8 + 2*t;
                float2 qr = __half22float2(*(const __half2*)(qres + col));
                float2 r;
                r.x = acc[mf][nf][2*rr+0] + __ldg(bias + col)   + qr.x;
                r.y = acc[mf][nf][2*rr+1] + __ldg(bias + col+1) + qr.y;
                *(float2*)(out + (size_t)gm*CC + col) = r;
            }
        }
    }
}

// =====================================================================
extern "C" void kernel_launch(void* const* d_in, const int* in_sizes, int n_in,
                              void* d_out, int out_size) {
    const float* before = (const float*)d_in[0];
    const float* after  = (const float*)d_in[1];
    const float* W_qkv  = (const float*)d_in[2];
    const float* ln_g   = (const float*)d_in[3];
    const float* ln_b   = (const float*)d_in[4];
    const float* W_proj = (const float*)d_in[5];
    const float* b_proj = (const float*)d_in[6];
    float* out = (float*)d_out;

    // 0) convert inputs to fp16
    preround_kernel<<<PR8/256, 256>>>(before, after, W_qkv, W_proj);

    // 1) QKV GEMM + register LN: grid (2304/128, 8192/128), 128 thr
    {
        cudaFuncSetAttribute(qkv_gemm_mma, cudaFuncAttributeMaxDynamicSharedMemorySize, GSMEMB);
        dim3 grid(QKV3/128, MROWS/128);
        qkv_gemm_mma<<<grid, 128, GSMEMB>>>(ln_g, ln_b);
    }
    // 2) Attention: 768 blocks, 128 thr (4 warps, 32 q-rows/warp)
    {
        cudaFuncSetAttribute(attn_mma, cudaFuncAttributeMaxDynamicSharedMemorySize, ATTN_SMEM);
        attn_mma<<<768, 128, ATTN_SMEM>>>();
    }
    // 3) Projection GEMM: grid (768/128, 8192/128), 256 thr
    {
        cudaFuncSetAttribute(proj_gemm_mma, cudaFuncAttributeMaxDynamicSharedMemorySize, GSMEMB);
        dim3 grid(CC/128, MROWS/128);
        proj_gemm_mma<<<grid, 256, GSMEMB>>>(b_proj, out);
    }
}